// round 2
// baseline (speedup 1.0000x reference)
#include <cuda_runtime.h>

// Causal FIR: y[row][t] = sum_{k=0}^{15} b[k] * x[row][t-k], zero initial state.
// x: [64, 480000] f32, b: [16] f32, y: [64, 480000] f32.
// HBM-bound: ~246 MB total traffic. One thread = 4 outputs, float4 in/out.

#define N_TAPS 16
#define T_LEN 480000
#define BATCH 64
#define OUTS_PER_THREAD 4

__global__ __launch_bounds__(256) void fir_kernel(
    const float* __restrict__ x,
    const float* __restrict__ b,
    float* __restrict__ y)
{
    const int row = blockIdx.y;
    const int t0  = (blockIdx.x * blockDim.x + threadIdx.x) * OUTS_PER_THREAD;
    if (t0 >= T_LEN) return;

    const float* __restrict__ xr = x + (size_t)row * T_LEN;

    // v[i] = x[t0 - 16 + i], i in [0,20). v[0] is unused slack so the 5
    // float4 loads stay 16B-aligned (t0 % 4 == 0, row stride % 4 == 0).
    float v[20];
    if (t0 >= N_TAPS) {
        const float4* __restrict__ p =
            reinterpret_cast<const float4*>(xr + t0 - 16);
        #pragma unroll
        for (int i = 0; i < 5; i++) {
            float4 f = p[i];
            v[4*i + 0] = f.x;
            v[4*i + 1] = f.y;
            v[4*i + 2] = f.z;
            v[4*i + 3] = f.w;
        }
    } else {
        // Row head: zero-padded shift register. Only 4 threads/row hit this.
        #pragma unroll
        for (int i = 0; i < 20; i++) {
            int idx = t0 - 16 + i;
            v[i] = (idx >= 0) ? xr[idx] : 0.0f;
        }
    }

    // Taps: uniform-address LDG, warp-broadcast, L1-resident after first warp.
    float taps[N_TAPS];
    #pragma unroll
    for (int k = 0; k < N_TAPS; k++) taps[k] = __ldg(b + k);

    // y[t0+j] = sum_k taps[k] * x[t0+j-k] = sum_k taps[k] * v[16+j-k]
    float acc[OUTS_PER_THREAD];
    #pragma unroll
    for (int j = 0; j < OUTS_PER_THREAD; j++) {
        float a = 0.0f;
        #pragma unroll
        for (int k = 0; k < N_TAPS; k++) {
            a = fmaf(taps[k], v[16 + j - k], a);
        }
        acc[j] = a;
    }

    float4 out;
    out.x = acc[0]; out.y = acc[1]; out.z = acc[2]; out.w = acc[3];
    *reinterpret_cast<float4*>(y + (size_t)row * T_LEN + t0) = out;
}

extern "C" void kernel_launch(void* const* d_in, const int* in_sizes, int n_in,
                              void* d_out, int out_size)
{
    const float* x = (const float*)d_in[0];
    const float* b = (const float*)d_in[1];
    float* y = (float*)d_out;

    const int threads = 256;
    const int threads_per_row = T_LEN / OUTS_PER_THREAD;          // 120000
    dim3 grid((threads_per_row + threads - 1) / threads, BATCH);  // (469, 64)
    fir_kernel<<<grid, threads>>>(x, b, y);
}

// round 3
// speedup vs baseline: 1.1648x; 1.1648x over previous
#include <cuda_runtime.h>

// Causal FIR: y[row][t] = sum_{k=0}^{15} b[k] * x[row][t-k], zero initial state.
// x: [64, 480000] f32, b: [16] f32, y: [64, 480000] f32.
// R2: L1tex-bound at OUTS=4 (L1=76.6%, DRAM=48%). OUTS=8 amortizes the
// 16-float halo: 6 LDG.128 + 2 STG.128 per 8 outputs (1.0 wavefront/output
// vs 1.5), cutting L1tex traffic ~33%.

#define N_TAPS 16
#define T_LEN 480000
#define BATCH 64
#define OUTS_PER_THREAD 8

__global__ __launch_bounds__(256) void fir_kernel(
    const float* __restrict__ x,
    const float* __restrict__ b,
    float* __restrict__ y)
{
    const int row = blockIdx.y;
    const int t0  = (blockIdx.x * blockDim.x + threadIdx.x) * OUTS_PER_THREAD;
    if (t0 >= T_LEN) return;

    const float* __restrict__ xr = x + (size_t)row * T_LEN;

    // v[i] = x[t0 - 16 + i], i in [0, 24). t0 % 8 == 0 so xr + t0 - 16 is
    // 32B-aligned: 6 aligned float4 loads, all front-batched (MLP=6).
    float v[24];
    if (t0 >= N_TAPS) {
        const float4* __restrict__ p =
            reinterpret_cast<const float4*>(xr + t0 - 16);
        #pragma unroll
        for (int i = 0; i < 6; i++) {
            float4 f = p[i];
            v[4*i + 0] = f.x;
            v[4*i + 1] = f.y;
            v[4*i + 2] = f.z;
            v[4*i + 3] = f.w;
        }
    } else {
        // Row head: zero-padded shift register. Only 2 threads/row (t0=0,8).
        #pragma unroll
        for (int i = 0; i < 24; i++) {
            int idx = t0 - 16 + i;
            v[i] = (idx >= 0) ? xr[idx] : 0.0f;
        }
    }

    // Taps: uniform-address LDG, warp-broadcast, L1-resident after warmup.
    float taps[N_TAPS];
    #pragma unroll
    for (int k = 0; k < N_TAPS; k++) taps[k] = __ldg(b + k);

    // y[t0+j] = sum_k taps[k] * v[16 + j - k]
    float acc[OUTS_PER_THREAD];
    #pragma unroll
    for (int j = 0; j < OUTS_PER_THREAD; j++) {
        float a = 0.0f;
        #pragma unroll
        for (int k = 0; k < N_TAPS; k++) {
            a = fmaf(taps[k], v[16 + j - k], a);
        }
        acc[j] = a;
    }

    float* yr = y + (size_t)row * T_LEN + t0;
    float4 o0, o1;
    o0.x = acc[0]; o0.y = acc[1]; o0.z = acc[2]; o0.w = acc[3];
    o1.x = acc[4]; o1.y = acc[5]; o1.z = acc[6]; o1.w = acc[7];
    reinterpret_cast<float4*>(yr)[0] = o0;
    reinterpret_cast<float4*>(yr)[1] = o1;
}

extern "C" void kernel_launch(void* const* d_in, const int* in_sizes, int n_in,
                              void* d_out, int out_size)
{
    const float* x = (const float*)d_in[0];
    const float* b = (const float*)d_in[1];
    float* y = (float*)d_out;

    const int threads = 256;
    const int threads_per_row = T_LEN / OUTS_PER_THREAD;          // 60000
    dim3 grid((threads_per_row + threads - 1) / threads, BATCH);  // (235, 64)
    fir_kernel<<<grid, threads>>>(x, b, y);
}